// round 10
// baseline (speedup 1.0000x reference)
#include <cuda_runtime.h>
#include <cuda_bf16.h>
#include <cstdint>

#define BATCH 4
#define MPER  4096
#define NTOT  (BATCH * MPER)
#define PAD_I (-999)
#define PAD_F (-999.0f)
#define CUT2  49.0f

#define JSPLIT 16
#define JCHUNK (MPER / JSPLIT)        // 256 j's per chunk = 128 packed jj's
#define PT_THREADS 128
#define RPT 4
#define ROWS_PER_BLOCK (PT_THREADS * RPT)   // 512

// Partial row-sums: [JSPLIT][NTOT]
__device__ float g_partial[JSPLIT * NTOT];
// Arrival counters, one per row-block (zero-init; reset by the reducing block)
__device__ int g_ctr[32];

// ---------------- packed f32x2 helpers (Blackwell) -------------------------
__device__ __forceinline__ uint64_t pk2(float f) {
    uint64_t r; uint32_t u = __float_as_uint(f);
    asm("mov.b64 %0, {%1, %1};" : "=l"(r) : "r"(u));
    return r;
}
__device__ __forceinline__ uint64_t pfma(uint64_t a, uint64_t b, uint64_t c) {
    uint64_t r;
    asm("fma.rn.f32x2 %0, %1, %2, %3;" : "=l"(r) : "l"(a), "l"(b), "l"(c));
    return r;
}

__device__ __forceinline__ float3 f3sub(float3 a, float3 b) {
    return make_float3(a.x - b.x, a.y - b.y, a.z - b.z);
}
__device__ __forceinline__ float3 f3cross(float3 a, float3 b) {
    return make_float3(a.y * b.z - a.z * b.y,
                       a.z * b.x - a.x * b.z,
                       a.x * b.y - a.y * b.x);
}
__device__ __forceinline__ float f3dot(float3 a, float3 b) {
    return a.x * b.x + a.y * b.y + a.z * b.z;
}
// gathered coordinate of logical atom-row n: coords[abatch[n], cidx[n]]
__device__ __forceinline__ float3 gat3(const float* __restrict__ coords,
                                       const int* __restrict__ abatch,
                                       const int* __restrict__ cidx, int n) {
    const float* p = coords + ((long)abatch[n] * MPER + cidx[n]) * 3;
    return make_float3(p[0], p[1], p[2]);
}

// ---------------------------------------------------------------------------
// Single fused kernel: 512 blocks (32 row-blocks x 16 j-chunks), 128 threads.
//   Phase A (warp-split): dihedral (w0) + partner columns (w1,w2) for 32 rows.
//   Phase B: self-gather j-tile to smem + 4 i-rows to registers.
//   Phase C: packed f32x2 screening + bitmask replay.
//   Phase D: last block per row-block reduces the 16 partials -> out col 1.
// ---------------------------------------------------------------------------
__global__ void __launch_bounds__(PT_THREADS)
ff_all(const float* __restrict__ coords,
       const int*   __restrict__ abatch,
       const int*   __restrict__ cidx,
       const int*   __restrict__ partners,
       const int*   __restrict__ aidx,
       float*       __restrict__ out) {
    // 2 float4 per packed jj: [x0 x1 y0 y1][z0 z1 w0-49 w1-49]
    __shared__ float4 sh[2 * (JCHUNK / 2)];
    __shared__ int s_last;

    int tid  = threadIdx.x;
    int wid  = tid >> 5;
    int lane = tid & 31;
    int rb = blockIdx.x >> 4;          // row-block 0..31
    int jc = blockIdx.x & 15;          // j-chunk  0..15
    int b  = rb >> 3;                  // 8 row-blocks per batch
    int jbase = b * MPER + jc * JCHUNK;

    // ---------------- Phase A: output tails (32 rows per block) ------------
    int orow = blockIdx.x * 32 + lane;
    if (wid == 0) {
        // dihedral -> out col 0
        int i0 = aidx[orow * 4 + 0];
        int i1 = aidx[orow * 4 + 1];
        int i2 = aidx[orow * 4 + 2];
        int i3 = aidx[orow * 4 + 3];
        if (i0 == PAD_I || i1 == PAD_I || i2 == PAD_I || i3 == PAD_I) {
            out[(long)orow * 8] = PAD_F;
        } else {
            float3 p1 = gat3(coords, abatch, cidx, i0);
            float3 p2 = gat3(coords, abatch, cidx, i1);
            float3 p3 = gat3(coords, abatch, cidx, i2);
            float3 p4 = gat3(coords, abatch, cidx, i3);
            float3 b1 = f3sub(p2, p1);
            float3 b2 = f3sub(p3, p2);
            float3 b3 = f3sub(p4, p3);
            float3 n1 = f3cross(b1, b2);
            float3 n2 = f3cross(b2, b3);
            float nb2 = sqrtf((b2.x * b2.x + b2.y * b2.y) + b2.z * b2.z);
            float inv = 1.0f / (nb2 + 1e-12f);
            float3 b2n = make_float3(b2.x * inv, b2.y * inv, b2.z * inv);
            float3 m1 = f3cross(n1, b2n);
            out[(long)orow * 8] = atan2f(f3dot(m1, n2), f3dot(n1, n2));
        }
    } else if (wid == 1 || wid == 2) {
        // partner column (wid-1) -> out cols 2..4 / 5..7
        int k  = wid - 1;
        int pb = abatch[orow];
        int p  = partners[orow * 2 + k];
        float px, py, pz;
        if (p == PAD_I) {
            px = PAD_F; py = PAD_F; pz = PAD_F;
        } else {
            const float* pp = coords + ((long)pb * MPER + p) * 3;
            px = pp[0]; py = pp[1]; pz = pp[2];
        }
        float* o = out + (long)orow * 8 + 2 + 3 * k;
        o[0] = px; o[1] = py; o[2] = pz;
    }

    // ---------------- Phase B: self-gather -------------------------------
    {
        int n0 = jbase + 2 * tid;
        int2 bb = *(const int2*)(abatch + n0);
        int2 cc = *(const int2*)(cidx + n0);
        const float* p0 = coords + ((long)bb.x * MPER + cc.x) * 3;
        const float* p1 = coords + ((long)bb.y * MPER + cc.y) * 3;
        float x0 = p0[0], y0 = p0[1], z0 = p0[2];
        float x1 = p1[0], y1 = p1[1], z1 = p1[2];
        float w0 = (x0 != PAD_F) ? (x0 * x0 + y0 * y0) + z0 * z0 : 3e30f;
        float w1 = (x1 != PAD_F) ? (x1 * x1 + y1 * y1) + z1 * z1 : 3e30f;
        sh[2 * tid]     = make_float4(x0, x1, y0, y1);
        sh[2 * tid + 1] = make_float4(z0, z1, w0 - CUT2, w1 - CUT2);
    }

    int row0 = rb * ROWS_PER_BLOCK + tid;
    float3   mp[RPT];
    float    msq[RPT];
    float    cmp[RPT];
    float    sum[RPT];
    uint64_t mx[RPT], my2[RPT], mz2[RPT], mh[RPT];
    #pragma unroll
    for (int k = 0; k < RPT; k++) {
        int r = row0 + k * PT_THREADS;
        const float* p = coords + ((long)abatch[r] * MPER + cidx[r]) * 3;
        float x = p[0], y = p[1], z = p[2];
        float sq = (x != PAD_F) ? (x * x + y * y) + z * z : 3e30f;
        mp[k]  = make_float3(x, y, z);
        msq[k] = sq;
        cmp[k] = CUT2 - sq;
        sum[k] = 0.0f;
        mx[k]  = pk2(x);
        my2[k] = pk2(y);
        mz2[k] = pk2(z);
        mh[k]  = pk2(-0.5f * sq);
    }
    const uint64_t NEG2 = pk2(-2.0f);
    const uint32_t sb   = (uint32_t)__cvta_generic_to_shared(sh);
    __syncthreads();

    // ---------------- Phase C: screening + replay -------------------------
    #pragma unroll
    for (int g = 0; g < 4; g++) {
        uint32_t mask = 0;
        #pragma unroll 4
        for (int jj = 0; jj < 32; jj++) {
            uint32_t ad = sb + (uint32_t)(g * 32 + jj) * 32u;
            uint64_t ux, uy, uz, uw;
            asm("ld.shared.v2.u64 {%0, %1}, [%2];"
                : "=l"(ux), "=l"(uy) : "r"(ad));
            asm("ld.shared.v2.u64 {%0, %1}, [%2];"
                : "=l"(uz), "=l"(uw) : "r"(ad + 16u));
            uint32_t orr = 0;
            #pragma unroll
            for (int k = 0; k < RPT; k++) {
                uint64_t t = pfma(mz2[k], uz, mh[k]);
                t = pfma(my2[k], uy, t);
                t = pfma(mx[k],  ux, t);
                uint64_t s = pfma(NEG2, t, uw);   // D - 49, packed x2
                orr |= (uint32_t)s | (uint32_t)(s >> 32);
            }
            mask = (mask << 1) | (orr >> 31);
        }
        while (mask) {
            int jjl = __clz(mask);
            mask &= ~(0x80000000u >> jjl);
            int idx = g * 32 + jjl;
            float4 A  = sh[2 * idx];       // x0 x1 y0 y1
            float4 Bv = sh[2 * idx + 1];   // z0 z1 w0-49 w1-49
            float w0 = Bv.z + CUT2;
            float w1 = Bv.w + CUT2;
            #pragma unroll
            for (int k = 0; k < RPT; k++) {
                float t0 = mp[k].z * Bv.x;
                t0 = fmaf(mp[k].y, A.z, t0);
                t0 = fmaf(mp[k].x, A.x, t0);
                float d20 = fmaf(-2.0f, t0, w0);
                if (d20 <= cmp[k])
                    sum[k] += sqrtf(fmaxf(d20 + msq[k], 0.0f) + 1e-12f);

                float t1 = mp[k].z * Bv.y;
                t1 = fmaf(mp[k].y, A.w, t1);
                t1 = fmaf(mp[k].x, A.y, t1);
                float d21 = fmaf(-2.0f, t1, w1);
                if (d21 <= cmp[k])
                    sum[k] += sqrtf(fmaxf(d21 + msq[k], 0.0f) + 1e-12f);
            }
        }
    }

    #pragma unroll
    for (int k = 0; k < RPT; k++)
        g_partial[jc * NTOT + row0 + k * PT_THREADS] = sum[k];

    // ---------------- Phase D: last-block reduction ------------------------
    __threadfence();               // make partials visible GPU-wide (all threads)
    __syncthreads();
    if (tid == 0)
        s_last = (atomicAdd(&g_ctr[rb], 1) == JSPLIT - 1);
    __syncthreads();
    if (s_last) {
        int base = rb * ROWS_PER_BLOCK;
        #pragma unroll
        for (int q = 0; q < RPT; q++) {
            int row = base + tid + q * PT_THREADS;
            float s = 0.0f;
            #pragma unroll
            for (int c = 0; c < JSPLIT; c++)
                s += __ldcg(&g_partial[c * NTOT + row]);
            out[(long)row * 8 + 1] = s;
        }
        if (tid == 0) g_ctr[rb] = 0;   // reset for next graph replay
    }
}

// ---------------------------------------------------------------------------
extern "C" void kernel_launch(void* const* d_in, const int* in_sizes, int n_in,
                              void* d_out, int out_size) {
    const float* coords   = (const float*)d_in[0];
    const int*   abatch   = (const int*)  d_in[1];
    const int*   cidx     = (const int*)  d_in[2];
    const int*   partners = (const int*)  d_in[3];
    const int*   aidx     = (const int*)  d_in[4];
    float*       out      = (float*)d_out;

    ff_all<<<32 * JSPLIT, PT_THREADS>>>(coords, abatch, cidx, partners, aidx, out);
}

// round 11
// speedup vs baseline: 1.0912x; 1.0912x over previous
#include <cuda_runtime.h>
#include <cuda_bf16.h>
#include <cstdint>

#define BATCH 4
#define MPER  4096
#define NTOT  (BATCH * MPER)
#define PAD_I (-999)
#define PAD_F (-999.0f)
#define CUT2  49.0f

#define JSPLIT 32
#define JCHUNK (MPER / JSPLIT)        // 128 j's per chunk = 64 packed jj's
#define NGROUP (JCHUNK / 64)          // 2 groups of 32 jj's
#define PT_THREADS 128
#define RPT 4
#define ROWS_PER_BLOCK (PT_THREADS * RPT)   // 512
#define NRB (NTOT / ROWS_PER_BLOCK)         // 32 row-blocks
#define NBLOCKS (NRB * JSPLIT)              // 1024
#define TAIL_ROWS (NTOT / NBLOCKS)          // 16 rows of output tail per block

// Partial row-sums: [JSPLIT][NTOT]
__device__ float g_partial[JSPLIT * NTOT];
// Arrival counters, one per row-block (zero-init; reset by the reducing block)
__device__ int g_ctr[NRB];

// ---------------- packed f32x2 helpers (Blackwell) -------------------------
__device__ __forceinline__ uint64_t pk2(float f) {
    uint64_t r; uint32_t u = __float_as_uint(f);
    asm("mov.b64 %0, {%1, %1};" : "=l"(r) : "r"(u));
    return r;
}
__device__ __forceinline__ uint64_t pfma(uint64_t a, uint64_t b, uint64_t c) {
    uint64_t r;
    asm("fma.rn.f32x2 %0, %1, %2, %3;" : "=l"(r) : "l"(a), "l"(b), "l"(c));
    return r;
}

__device__ __forceinline__ float3 f3sub(float3 a, float3 b) {
    return make_float3(a.x - b.x, a.y - b.y, a.z - b.z);
}
__device__ __forceinline__ float3 f3cross(float3 a, float3 b) {
    return make_float3(a.y * b.z - a.z * b.y,
                       a.z * b.x - a.x * b.z,
                       a.x * b.y - a.y * b.x);
}
__device__ __forceinline__ float f3dot(float3 a, float3 b) {
    return a.x * b.x + a.y * b.y + a.z * b.z;
}
__device__ __forceinline__ float3 gat3(const float* __restrict__ coords,
                                       const int* __restrict__ abatch,
                                       const int* __restrict__ cidx, int n) {
    const float* p = coords + ((long)abatch[n] * MPER + cidx[n]) * 3;
    return make_float3(p[0], p[1], p[2]);
}

// ---------------------------------------------------------------------------
// Single fused kernel: 1024 blocks (32 row-blocks x 32 j-chunks), 128 threads.
//   Phase A (warp-split): dihedral (w0) + partner columns (w1,w2), 16 rows.
//   Phase B: self-gather j-tile to smem + 4 i-rows to registers.
//   Phase C: packed f32x2 screening + bitmask replay.
//   Phase D: last block per row-block reduces the 32 partials -> out col 1.
// ---------------------------------------------------------------------------
__global__ void __launch_bounds__(PT_THREADS)
ff_all(const float* __restrict__ coords,
       const int*   __restrict__ abatch,
       const int*   __restrict__ cidx,
       const int*   __restrict__ partners,
       const int*   __restrict__ aidx,
       float*       __restrict__ out) {
    // 2 float4 per packed jj: [x0 x1 y0 y1][z0 z1 w0-49 w1-49]
    __shared__ float4 sh[2 * (JCHUNK / 2)];
    __shared__ int s_last;

    int tid  = threadIdx.x;
    int wid  = tid >> 5;
    int lane = tid & 31;
    int rb = blockIdx.x >> 5;          // row-block 0..31
    int jc = blockIdx.x & 31;          // j-chunk  0..31
    int b  = rb >> 3;                  // 8 row-blocks per batch
    int jbase = b * MPER + jc * JCHUNK;

    // ---------------- Phase A: output tails (16 rows per block) ------------
    int orow = blockIdx.x * TAIL_ROWS + (lane & 15);
    if (lane < 16) {
        if (wid == 0) {
            // dihedral -> out col 0
            int i0 = aidx[orow * 4 + 0];
            int i1 = aidx[orow * 4 + 1];
            int i2 = aidx[orow * 4 + 2];
            int i3 = aidx[orow * 4 + 3];
            if (i0 == PAD_I || i1 == PAD_I || i2 == PAD_I || i3 == PAD_I) {
                out[(long)orow * 8] = PAD_F;
            } else {
                float3 p1 = gat3(coords, abatch, cidx, i0);
                float3 p2 = gat3(coords, abatch, cidx, i1);
                float3 p3 = gat3(coords, abatch, cidx, i2);
                float3 p4 = gat3(coords, abatch, cidx, i3);
                float3 b1 = f3sub(p2, p1);
                float3 b2 = f3sub(p3, p2);
                float3 b3 = f3sub(p4, p3);
                float3 n1 = f3cross(b1, b2);
                float3 n2 = f3cross(b2, b3);
                float nb2 = sqrtf((b2.x * b2.x + b2.y * b2.y) + b2.z * b2.z);
                float inv = 1.0f / (nb2 + 1e-12f);
                float3 b2n = make_float3(b2.x * inv, b2.y * inv, b2.z * inv);
                float3 m1 = f3cross(n1, b2n);
                out[(long)orow * 8] = atan2f(f3dot(m1, n2), f3dot(n1, n2));
            }
        } else if (wid == 1 || wid == 2) {
            // partner column (wid-1) -> out cols 2..4 / 5..7
            int k  = wid - 1;
            int pb = abatch[orow];
            int p  = partners[orow * 2 + k];
            float px, py, pz;
            if (p == PAD_I) {
                px = PAD_F; py = PAD_F; pz = PAD_F;
            } else {
                const float* pp = coords + ((long)pb * MPER + p) * 3;
                px = pp[0]; py = pp[1]; pz = pp[2];
            }
            float* o = out + (long)orow * 8 + 2 + 3 * k;
            o[0] = px; o[1] = py; o[2] = pz;
        }
    }

    // ---------------- Phase B: self-gather -------------------------------
    if (tid < JCHUNK / 2) {            // 64 packed slots
        int n0 = jbase + 2 * tid;
        int2 bb = *(const int2*)(abatch + n0);
        int2 cc = *(const int2*)(cidx + n0);
        const float* p0 = coords + ((long)bb.x * MPER + cc.x) * 3;
        const float* p1 = coords + ((long)bb.y * MPER + cc.y) * 3;
        float x0 = p0[0], y0 = p0[1], z0 = p0[2];
        float x1 = p1[0], y1 = p1[1], z1 = p1[2];
        float w0 = (x0 != PAD_F) ? (x0 * x0 + y0 * y0) + z0 * z0 : 3e30f;
        float w1 = (x1 != PAD_F) ? (x1 * x1 + y1 * y1) + z1 * z1 : 3e30f;
        sh[2 * tid]     = make_float4(x0, x1, y0, y1);
        sh[2 * tid + 1] = make_float4(z0, z1, w0 - CUT2, w1 - CUT2);
    }

    int row0 = rb * ROWS_PER_BLOCK + tid;
    float3   mp[RPT];
    float    msq[RPT];
    float    cmp[RPT];
    float    sum[RPT];
    uint64_t mx[RPT], my2[RPT], mz2[RPT], mh[RPT];
    #pragma unroll
    for (int k = 0; k < RPT; k++) {
        int r = row0 + k * PT_THREADS;
        const float* p = coords + ((long)abatch[r] * MPER + cidx[r]) * 3;
        float x = p[0], y = p[1], z = p[2];
        float sq = (x != PAD_F) ? (x * x + y * y) + z * z : 3e30f;
        mp[k]  = make_float3(x, y, z);
        msq[k] = sq;
        cmp[k] = CUT2 - sq;
        sum[k] = 0.0f;
        mx[k]  = pk2(x);
        my2[k] = pk2(y);
        mz2[k] = pk2(z);
        mh[k]  = pk2(-0.5f * sq);
    }
    const uint64_t NEG2 = pk2(-2.0f);
    const uint32_t sb   = (uint32_t)__cvta_generic_to_shared(sh);
    __syncthreads();

    // ---------------- Phase C: screening + replay -------------------------
    #pragma unroll
    for (int g = 0; g < NGROUP; g++) {
        uint32_t mask = 0;
        #pragma unroll 4
        for (int jj = 0; jj < 32; jj++) {
            uint32_t ad = sb + (uint32_t)(g * 32 + jj) * 32u;
            uint64_t ux, uy, uz, uw;
            asm("ld.shared.v2.u64 {%0, %1}, [%2];"
                : "=l"(ux), "=l"(uy) : "r"(ad));
            asm("ld.shared.v2.u64 {%0, %1}, [%2];"
                : "=l"(uz), "=l"(uw) : "r"(ad + 16u));
            uint32_t orr = 0;
            #pragma unroll
            for (int k = 0; k < RPT; k++) {
                uint64_t t = pfma(mz2[k], uz, mh[k]);
                t = pfma(my2[k], uy, t);
                t = pfma(mx[k],  ux, t);
                uint64_t s = pfma(NEG2, t, uw);   // D - 49, packed x2
                orr |= (uint32_t)s | (uint32_t)(s >> 32);
            }
            mask = (mask << 1) | (orr >> 31);
        }
        while (mask) {
            int jjl = __clz(mask);
            mask &= ~(0x80000000u >> jjl);
            int idx = g * 32 + jjl;
            float4 A  = sh[2 * idx];       // x0 x1 y0 y1
            float4 Bv = sh[2 * idx + 1];   // z0 z1 w0-49 w1-49
            float w0 = Bv.z + CUT2;
            float w1 = Bv.w + CUT2;
            #pragma unroll
            for (int k = 0; k < RPT; k++) {
                float t0 = mp[k].z * Bv.x;
                t0 = fmaf(mp[k].y, A.z, t0);
                t0 = fmaf(mp[k].x, A.x, t0);
                float d20 = fmaf(-2.0f, t0, w0);
                if (d20 <= cmp[k])
                    sum[k] += sqrtf(fmaxf(d20 + msq[k], 0.0f) + 1e-12f);

                float t1 = mp[k].z * Bv.y;
                t1 = fmaf(mp[k].y, A.w, t1);
                t1 = fmaf(mp[k].x, A.y, t1);
                float d21 = fmaf(-2.0f, t1, w1);
                if (d21 <= cmp[k])
                    sum[k] += sqrtf(fmaxf(d21 + msq[k], 0.0f) + 1e-12f);
            }
        }
    }

    #pragma unroll
    for (int k = 0; k < RPT; k++)
        g_partial[jc * NTOT + row0 + k * PT_THREADS] = sum[k];

    // ---------------- Phase D: last-block reduction ------------------------
    __threadfence();               // make partials visible GPU-wide
    __syncthreads();
    if (tid == 0)
        s_last = (atomicAdd(&g_ctr[rb], 1) == JSPLIT - 1);
    __syncthreads();
    if (s_last) {
        int base = rb * ROWS_PER_BLOCK;
        #pragma unroll
        for (int q = 0; q < RPT; q++) {
            int row = base + tid + q * PT_THREADS;
            float s = 0.0f;
            #pragma unroll
            for (int c = 0; c < JSPLIT; c++)
                s += __ldcg(&g_partial[c * NTOT + row]);
            out[(long)row * 8 + 1] = s;
        }
        if (tid == 0) g_ctr[rb] = 0;   // reset for next graph replay
    }
}

// ---------------------------------------------------------------------------
extern "C" void kernel_launch(void* const* d_in, const int* in_sizes, int n_in,
                              void* d_out, int out_size) {
    const float* coords   = (const float*)d_in[0];
    const int*   abatch   = (const int*)  d_in[1];
    const int*   cidx     = (const int*)  d_in[2];
    const int*   partners = (const int*)  d_in[3];
    const int*   aidx     = (const int*)  d_in[4];
    float*       out      = (float*)d_out;

    ff_all<<<NBLOCKS, PT_THREADS>>>(coords, abatch, cidx, partners, aidx, out);
}